// round 15
// baseline (speedup 1.0000x reference)
#include <cuda_runtime.h>
#include <cuda.h>
#include <cstdint>

#define MTOT 8192
#define LW 64
#define RW 100
#define CD 128
#define CSTR 104

typedef unsigned int u32;

// smem (u32 words):
// conf [0, 6656)                     (written after mainloop; dead during it)
// raw TMA slots [6656, 12032): slot = A 64x16 f32 (1024) + B 104x16 (1664)
//   raw slot1 B [10368, 12032) ends holding ch112..127 -> ff source
#define OFF_CONF 0
#define OFF_RAW  6656
#define RAWSLOT  2688
#define OFF_RINV 12032
#define OFF_CINV 12096
#define OFF_REDV 12224
#define OFF_REDI 12232
#define OFF_MBAR 12240
#define SMEM_WORDS 12244
#define SMEM_BYTES (SMEM_WORDS * 4)
#define CHUNK_BYTES ((1024 + 1664) * 4)

// bf16 pair split: hi = top-16 truncation (PRMT pack), lo = exact remainder.
__device__ __forceinline__ void bfsplit2(float x, float y, u32& hp, u32& lp) {
    u32 bx = __float_as_uint(x), by = __float_as_uint(y);
    float lxf = x - __uint_as_float(bx & 0xFFFF0000u);
    float lyf = y - __uint_as_float(by & 0xFFFF0000u);
    asm("prmt.b32 %0, %1, %2, 0x7632;" : "=r"(hp) : "r"(bx), "r"(by));
    asm("prmt.b32 %0, %1, %2, 0x7632;" : "=r"(lp)
        : "r"(__float_as_uint(lxf)), "r"(__float_as_uint(lyf)));
}
__device__ __forceinline__ void mma_bf16(float c[4],
                                         u32 a0, u32 a1, u32 a2, u32 a3,
                                         u32 b0, u32 b1) {
    asm volatile(
        "mma.sync.aligned.m16n8k16.row.col.f32.bf16.bf16.f32 "
        "{%0,%1,%2,%3}, {%4,%5,%6,%7}, {%8,%9}, {%0,%1,%2,%3};"
        : "+f"(c[0]), "+f"(c[1]), "+f"(c[2]), "+f"(c[3])
        : "r"(a0), "r"(a1), "r"(a2), "r"(a3), "r"(b0), "r"(b1));
}
#define MBAR_INIT(a, c) asm volatile("mbarrier.init.shared.b64 [%0], %1;" :: "r"(a), "r"(c) : "memory")
#define MBAR_TX(a, b)   asm volatile("mbarrier.arrive.expect_tx.shared.b64 _, [%0], %1;" :: "r"(a), "r"(b) : "memory")
#define MBAR_WAIT(a, p) asm volatile("{\n\t.reg .pred P;\n\tW_%=: mbarrier.try_wait.parity.acquire.cta.shared::cta.b64 P, [%0], %1, 0x989680;\n\t@P bra.uni D_%=;\n\tbra.uni W_%=;\n\tD_%=:\n\t}" :: "r"(a), "r"(p) : "memory")
#define TMA2D(d, mp, cx, cy, mb) asm volatile("cp.async.bulk.tensor.2d.shared::cta.global.tile.mbarrier::complete_tx::bytes [%0], [%1, {%2, %3}], [%4];" :: "r"(d), "l"(mp), "r"(cx), "r"(cy), "r"(mb) : "memory")
#define SWZ64(o) ((o) ^ (((o) >> 3) & 0x30))

__global__ void __launch_bounds__(256, 4)
fine_matching_kernel(const float* __restrict__ feat0,
                     const float* __restrict__ feat1,
                     const float* __restrict__ mk0,
                     const float* __restrict__ mk1,
                     float* __restrict__ out,
                     const __grid_constant__ CUtensorMap tmap0,
                     const __grid_constant__ CUtensorMap tmap1)
{
    extern __shared__ float smem[];
    float* conf = smem + OFF_CONF;
    float* rinv = smem + OFF_RINV;
    float* cinv = smem + OFF_CINV;
    float* redv = smem + OFF_REDV;
    int*   redi = (int*)(smem + OFF_REDI);

    const int m = blockIdx.x, tid = threadIdx.x;
    const int warp = tid >> 5, lane = tid & 31;

    u32 sb0;
    { unsigned long long gp = __cvta_generic_to_shared(smem); sb0 = (u32)gp; }
    const u32 rawbar0 = sb0 + OFF_MBAR * 4, rawbar1 = rawbar0 + 8;

    const float* f0base = feat0 + (size_t)m * (LW * CD);

    if (tid == 0) {
        MBAR_INIT(rawbar0, 1); MBAR_INIT(rawbar1, 1);
    }
    __syncthreads();
    if (tid == 0) {
        MBAR_TX(rawbar0, CHUNK_BYTES);
        TMA2D(sb0 + OFF_RAW * 4,               &tmap0, 0,  m * LW, rawbar0);
        TMA2D(sb0 + (OFF_RAW + 1024) * 4,      &tmap1, 0,  m * RW, rawbar0);
        MBAR_TX(rawbar1, CHUNK_BYTES);
        TMA2D(sb0 + (OFF_RAW + RAWSLOT) * 4,        &tmap0, 16, m * LW, rawbar1);
        TMA2D(sb0 + (OFF_RAW + RAWSLOT + 1024) * 4, &tmap1, 16, m * RW, rawbar1);
    }

    // ---- mainloop: 8 chunks x 16 ch, fragment-direct register bf16 split ----
    const int gid  = lane >> 2;
    const int ctid = lane & 3;
    const int wm   = warp & 3;
    const int wn   = warp >> 2;
    const int l0   = wm * 16;
    const int nbase = wn * 56;   // wn0: 7 n-tiles, wn1: 6

    float c[7][4];
    #pragma unroll
    for (int j = 0; j < 7; ++j)
        { c[j][0] = 0.f; c[j][1] = 0.f; c[j][2] = 0.f; c[j][3] = 0.f; }

    #pragma unroll 1
    for (int ck = 0; ck < 8; ++ck) {
        const int slot = ck & 1;
        MBAR_WAIT(slot ? rawbar1 : rawbar0, (ck >> 1) & 1);
        const char* rawA = (const char*)(smem + OFF_RAW + slot * RAWSLOT);
        const char* rawB = rawA + 4096;
        const bool last = (ck == 7);   // k 8..15 = ch 120..127: excluded

        // A fragments: rows l0+gid, l0+gid+8; k pairs 2ctid and 8+2ctid
        u32 ah0, ah1, ah2, ah3, al0, al1, al2, al3;
        {
            const u32 rb = (u32)((l0 + gid) * 64 + ctid * 8);
            float2 v0 = *(const float2*)(rawA + SWZ64(rb));
            float2 v1 = *(const float2*)(rawA + SWZ64(rb + 512));       // +8 rows
            float2 v2 = *(const float2*)(rawA + SWZ64(rb + 32));        // k+8
            float2 v3 = *(const float2*)(rawA + SWZ64(rb + 512 + 32));
            bfsplit2(v0.x, v0.y, ah0, al0);
            bfsplit2(v1.x, v1.y, ah1, al1);
            bfsplit2(v2.x, v2.y, ah2, al2);
            bfsplit2(v3.x, v3.y, ah3, al3);
            if (last) { ah2 = al2 = ah3 = al3 = 0u; }
        }

        #define BTILE(cj, nr) do {                                             \
            const u32 _bb = (u32)((nr) * 64 + ctid * 8);                        \
            float2 _w0 = *(const float2*)(rawB + SWZ64(_bb));                   \
            float2 _w1 = *(const float2*)(rawB + SWZ64(_bb + 32));              \
            u32 _bh0, _bl0, _bh1, _bl1;                                         \
            bfsplit2(_w0.x, _w0.y, _bh0, _bl0);                                 \
            bfsplit2(_w1.x, _w1.y, _bh1, _bl1);                                 \
            if (last) { _bh1 = 0u; _bl1 = 0u; }                                 \
            mma_bf16(cj, ah0, ah1, ah2, ah3, _bh0, _bh1);                       \
            mma_bf16(cj, ah0, ah1, ah2, ah3, _bl0, _bl1);                       \
            mma_bf16(cj, al0, al1, al2, al3, _bh0, _bh1);                       \
        } while (0)

        #pragma unroll
        for (int j = 0; j < 6; ++j)
            BTILE(c[j], nbase + j * 8 + gid);
        if (wn == 0)                       // uniform per warp
            BTILE(c[6], nbase + 48 + gid);

        __syncthreads();                   // slot fully consumed
        if (ck < 6 && tid == 0) {
            const u32 rb = slot ? rawbar1 : rawbar0;
            MBAR_TX(rb, CHUNK_BYTES);
            TMA2D(sb0 + (OFF_RAW + slot * RAWSLOT) * 4,        &tmap0, (ck + 2) * 16, m * LW, rb);
            TMA2D(sb0 + (OFF_RAW + slot * RAWSLOT + 1024) * 4, &tmap1, (ck + 2) * 16, m * RW, rb);
        }
    }

    // ---- store conf from C fragments (x 1/128 exact) ----
    {
        const float sc = 0.0078125f;
        const int rowa = (l0 + gid) * CSTR + 2 * ctid;
        const int ntiles = wn ? 6 : 7;
        #pragma unroll
        for (int j = 0; j < 7; ++j) {
            if (j < ntiles) {
                int o = rowa + nbase + 8 * j;
                *(float2*)&conf[o]            = make_float2(c[j][0]*sc, c[j][1]*sc);
                *(float2*)&conf[o + 8 * CSTR] = make_float2(c[j][2]*sc, c[j][3]*sc);
            }
        }
    }
    __syncthreads();

    // ---- global Vmax (garbage cols fine: shift-invariant) ----
    float vm = -1e30f;
    #pragma unroll
    for (int i = 0; i < 26; ++i) vm = fmaxf(vm, conf[tid + i * 256]);
    #pragma unroll
    for (int o = 16; o; o >>= 1) vm = fmaxf(vm, __shfl_xor_sync(~0u, vm, o));
    if (lane == 0) redv[warp] = vm;
    __syncthreads();
    float vmax = redv[0];
    #pragma unroll
    for (int w = 1; w < 8; ++w) vmax = fmaxf(vmax, redv[w]);

    // ---- E pass (in place) + row sums; cols 100..103 excluded ----
    #pragma unroll 2
    for (int q2 = 0; q2 < 8; ++q2) {
        int l = warp * 8 + q2;
        float* row = &conf[l * CSTR];
        float e0 = __expf(row[lane]      - vmax);
        float e1 = __expf(row[lane + 32] - vmax);
        float e2 = __expf(row[lane + 64] - vmax);
        row[lane] = e0; row[lane + 32] = e1; row[lane + 64] = e2;
        float s = e0 + e1 + e2;
        if (lane < 4) {
            float e3 = __expf(row[lane + 96] - vmax);
            row[lane + 96] = e3; s += e3;
        }
        #pragma unroll
        for (int o = 16; o; o >>= 1) s += __shfl_xor_sync(~0u, s, o);
        if (lane == 0) rinv[l] = 1.f / s;
    }
    __syncthreads();

    // ---- col sums ----
    {
        int col = tid >> 1, half = tid & 1;
        float s = 0.f;
        const float* p = &conf[(half * 32) * CSTR + col];
        #pragma unroll 8
        for (int l = 0; l < 32; ++l) s += p[l * CSTR];
        float tot = s + __shfl_xor_sync(~0u, s, 1);
        if (!half) cinv[col] = 1.f / tot;
    }
    __syncthreads();

    // ---- cropped sm write + argmax ----
    const int rc = tid & 63;
    const int r  = (rc >> 3) * 10 + (rc & 7) + 11;
    const float ci = cinv[r];
    const int lb = tid >> 6;
    float bv = -1e30f; int bi = 0;
    float* outm = out + (size_t)m * 4096;
    #pragma unroll
    for (int e8 = 0; e8 < 16; ++e8) {
        int l = e8 * 4 + lb;
        float e = conf[l * CSTR + r];
        float s = e * e * rinv[l] * ci;
        int flat = l * 64 + rc;
        outm[flat] = s;
        if (s > bv) { bv = s; bi = flat; }
    }
    #pragma unroll
    for (int o = 16; o; o >>= 1) {
        float v2 = __shfl_xor_sync(~0u, bv, o);
        int   i2 = __shfl_xor_sync(~0u, bi, o);
        if (v2 > bv || (v2 == bv && i2 < bi)) { bv = v2; bi = i2; }
    }
    if (lane == 0) { redv[warp] = bv; redi[warp] = bi; }
    __syncthreads();

    // ---- warp 0: final reduce + epilogue ----
    if (warp == 0) {
        float v = (lane < 8) ? redv[lane] : -1e30f;
        int   i = (lane < 8) ? redi[lane] : 0x7fffffff;
        #pragma unroll
        for (int o = 4; o; o >>= 1) {
            float v2 = __shfl_xor_sync(~0u, v, o);
            int   i2 = __shfl_xor_sync(~0u, i, o);
            if (v2 > v || (v2 == v && i2 < i)) { v = v2; i = i2; }
        }
        if (lane == 0) {
            int idx = i;
            int il = idx >> 6, ir = idx & 63;
            float dlx = (float)(il & 7) - 3.5f, dly = (float)(il >> 3) - 3.5f;
            float drx = (float)(ir & 7) - 3.5f, dry = (float)(ir >> 3) - 3.5f;

            float4 av0 = __ldg((const float4*)(f0base + il * CD + 120));
            float4 av1 = __ldg((const float4*)(f0base + il * CD + 124));
            float av[8] = {av0.x, av0.y, av0.z, av0.w, av1.x, av1.y, av1.z, av1.w};

            // ff from raw slot1 B box (chunk 7 = ch 112..127): ch 120+t -> col 8+t
            const char* ffbox = (const char*)(smem + OFF_RAW + RAWSLOT + 1024);
            float p[9];
            int ib = ir >> 3, jb = ir & 7;
            #pragma unroll
            for (int di = 0; di < 3; ++di) {
                int ii = ib + di - 1; ii = (ii < 0) ? ii + 10 : ((ii > 9) ? ii - 10 : ii);
                #pragma unroll
                for (int dj = 0; dj < 3; ++dj) {
                    int jj = jb + dj - 1; jj = (jj < 0) ? jj + 10 : ((jj > 9) ? jj - 10 : jj);
                    int rr2 = ii * 10 + jj;
                    float s = 0.f;
                    #pragma unroll
                    for (int t = 0; t < 8; ++t)
                        s += av[t] * *(const float*)(ffbox + SWZ64((u32)(rr2 * 64 + (8 + t) * 4)));
                    p[di * 3 + dj] = s;
                }
            }
            float mx = p[0];
            #pragma unroll
            for (int t = 1; t < 9; ++t) mx = fmaxf(mx, p[t]);
            const float escale = 0.035355339059327373f;  // (1/sqrt8)/TEMP
            float h[9], se = 0.f;
            #pragma unroll
            for (int t = 0; t < 9; ++t) { h[t] = __expf((p[t] - mx) * escale); se += h[t]; }
            float inv = 1.f / se;
            float ex = 0.f, ey = 0.f;
            #pragma unroll
            for (int di = 0; di < 3; ++di)
                #pragma unroll
                for (int dj = 0; dj < 3; ++dj) {
                    ex += h[di * 3 + dj] * (float)(dj - 1);
                    ey += h[di * 3 + dj] * (float)(di - 1);
                }
            ex *= inv; ey *= inv;

            float mk0x = mk0[2 * m], mk0y = mk0[2 * m + 1];
            float mk1x = mk1[2 * m], mk1y = mk1[2 * m + 1];
            size_t base = (size_t)MTOT * 4096;
            out[base + 2 * m]     = mk0x + dlx * 2.f;
            out[base + 2 * m + 1] = mk0y + dly * 2.f;
            out[base + 2 * MTOT + 2 * m]     = mk1x + drx * 2.f + ex * 2.f;
            out[base + 2 * MTOT + 2 * m + 1] = mk1y + dry * 2.f + ey * 2.f;
        }
    }
}

typedef CUresult (*PFN_encodeTiled)(
    CUtensorMap*, CUtensorMapDataType, cuuint32_t, void*,
    const cuuint64_t*, const cuuint64_t*, const cuuint32_t*, const cuuint32_t*,
    CUtensorMapInterleave, CUtensorMapSwizzle, CUtensorMapL2promotion,
    CUtensorMapFloatOOBfill);

extern "C" void kernel_launch(void* const* d_in, const int* in_sizes, int n_in,
                              void* d_out, int out_size)
{
    const float* feat0 = (const float*)d_in[0];
    const float* feat1 = (const float*)d_in[1];
    const float* mk0   = (const float*)d_in[2];
    const float* mk1   = (const float*)d_in[3];
    float* out = (float*)d_out;

    void* fn = nullptr;
    cudaDriverEntryPointQueryResult qres;
    cudaGetDriverEntryPoint("cuTensorMapEncodeTiled", &fn, cudaEnableDefault, &qres);
    PFN_encodeTiled enc = (PFN_encodeTiled)fn;

    CUtensorMap map0, map1;
    {
        cuuint64_t dims[2] = {CD, (cuuint64_t)MTOT * LW};
        cuuint64_t strd[1] = {CD * 4};
        cuuint32_t box[2]  = {16, LW};
        cuuint32_t els[2]  = {1, 1};
        enc(&map0, CU_TENSOR_MAP_DATA_TYPE_FLOAT32, 2, (void*)feat0,
            dims, strd, box, els, CU_TENSOR_MAP_INTERLEAVE_NONE,
            CU_TENSOR_MAP_SWIZZLE_64B, CU_TENSOR_MAP_L2_PROMOTION_L2_128B,
            CU_TENSOR_MAP_FLOAT_OOB_FILL_NONE);
    }
    {
        cuuint64_t dims[2] = {CD, (cuuint64_t)MTOT * RW};
        cuuint64_t strd[1] = {CD * 4};
        cuuint32_t box[2]  = {16, 104};
        cuuint32_t els[2]  = {1, 1};
        enc(&map1, CU_TENSOR_MAP_DATA_TYPE_FLOAT32, 2, (void*)feat1,
            dims, strd, box, els, CU_TENSOR_MAP_INTERLEAVE_NONE,
            CU_TENSOR_MAP_SWIZZLE_64B, CU_TENSOR_MAP_L2_PROMOTION_L2_128B,
            CU_TENSOR_MAP_FLOAT_OOB_FILL_NONE);
    }

    cudaFuncSetAttribute(fine_matching_kernel,
                         cudaFuncAttributeMaxDynamicSharedMemorySize, SMEM_BYTES);
    fine_matching_kernel<<<MTOT, 256, SMEM_BYTES>>>(feat0, feat1, mk0, mk1, out,
                                                    map0, map1);
}

// round 16
// speedup vs baseline: 1.2607x; 1.2607x over previous
#include <cuda_runtime.h>
#include <cuda.h>
#include <cuda_fp16.h>
#include <cstdint>

#define MTOT 8192
#define LW 64
#define RW 100
#define CD 128
#define CSTR 104
#define CROW 12      // operand array row stride (u32)

typedef unsigned int u32;

// smem (u32 words):
// fp16 operand slots: slot = AH 768 | AL 768 | BH 1248 = 2784
//   slot0 [0,2784) slot1 [2784,5568); conf 64x104=6656 aliases [0,6656) at end
// raw TMA slots [6656,12032): slot = A 64x16 f32 (1024) + B 104x16 (1664)
//   raw slot1 B [10368,12032) ends holding ch112..127 -> ff source
#define AH0 0
#define AL0 768
#define BH0 1536
#define SLOT_W 2784
#define OFF_RAW 6656
#define RAWSLOT 2688
#define OFF_RINV 12032
#define OFF_CINV 12096
#define OFF_REDV 12224
#define OFF_REDI 12232
#define OFF_MBAR 12240
#define SMEM_WORDS 12244
#define SMEM_BYTES (SMEM_WORDS * 4)
#define CHUNK_BYTES ((1024 + 1664) * 4)

// asymmetric fp16 split: hp = fp16x2(x,y) (x in low half), lp = fp16x2 of
// exact residuals. a = ah + al captures 22 mantissa bits; B uses hp only.
__device__ __forceinline__ void f16split2(float x, float y, u32& hp, u32& lp) {
    asm("cvt.rn.f16x2.f32 %0, %1, %2;" : "=r"(hp) : "f"(y), "f"(x));
    __half2 h2 = *reinterpret_cast<__half2*>(&hp);
    float rx = x - __low2float(h2);
    float ry = y - __high2float(h2);
    asm("cvt.rn.f16x2.f32 %0, %1, %2;" : "=r"(lp) : "f"(ry), "f"(rx));
}
__device__ __forceinline__ u32 f16pack2(float x, float y) {
    u32 r; asm("cvt.rn.f16x2.f32 %0, %1, %2;" : "=r"(r) : "f"(y), "f"(x));
    return r;
}
__device__ __forceinline__ void mma_f16(float c[4],
                                        u32 a0, u32 a1, u32 a2, u32 a3,
                                        u32 b0, u32 b1) {
    asm volatile(
        "mma.sync.aligned.m16n8k16.row.col.f32.f16.f16.f32 "
        "{%0,%1,%2,%3}, {%4,%5,%6,%7}, {%8,%9}, {%0,%1,%2,%3};"
        : "+f"(c[0]), "+f"(c[1]), "+f"(c[2]), "+f"(c[3])
        : "r"(a0), "r"(a1), "r"(a2), "r"(a3), "r"(b0), "r"(b1));
}
#define MBAR_INIT(a, c) asm volatile("mbarrier.init.shared.b64 [%0], %1;" :: "r"(a), "r"(c) : "memory")
#define MBAR_TX(a, b)   asm volatile("mbarrier.arrive.expect_tx.shared.b64 _, [%0], %1;" :: "r"(a), "r"(b) : "memory")
#define MBAR_WAIT(a, p) asm volatile("{\n\t.reg .pred P;\n\tW_%=: mbarrier.try_wait.parity.acquire.cta.shared::cta.b64 P, [%0], %1, 0x989680;\n\t@P bra.uni D_%=;\n\tbra.uni W_%=;\n\tD_%=:\n\t}" :: "r"(a), "r"(p) : "memory")
#define TMA2D(d, mp, cx, cy, mb) asm volatile("cp.async.bulk.tensor.2d.shared::cta.global.tile.mbarrier::complete_tx::bytes [%0], [%1, {%2, %3}], [%4];" :: "r"(d), "l"(mp), "r"(cx), "r"(cy), "r"(mb) : "memory")
#define SWZ64(o) ((o) ^ (((o) >> 3) & 0x30))

__global__ void __launch_bounds__(256, 4)
fine_matching_kernel(const float* __restrict__ feat0,
                     const float* __restrict__ feat1,
                     const float* __restrict__ mk0,
                     const float* __restrict__ mk1,
                     float* __restrict__ out,
                     const __grid_constant__ CUtensorMap tmap0,
                     const __grid_constant__ CUtensorMap tmap1)
{
    extern __shared__ float smem[];
    u32*   cv   = (u32*)smem;
    float* conf = smem;
    float* rinv = smem + OFF_RINV;
    float* cinv = smem + OFF_CINV;
    float* redv = smem + OFF_REDV;
    int*   redi = (int*)(smem + OFF_REDI);

    const int m = blockIdx.x, tid = threadIdx.x;
    const int warp = tid >> 5, lane = tid & 31;

    u32 sb0;
    { unsigned long long gp = __cvta_generic_to_shared(smem); sb0 = (u32)gp; }
    const u32 rawbar0 = sb0 + OFF_MBAR * 4, rawbar1 = rawbar0 + 8;

    const float* f0base = feat0 + (size_t)m * (LW * CD);

    if (tid == 0) { MBAR_INIT(rawbar0, 1); MBAR_INIT(rawbar1, 1); }
    __syncthreads();
    if (tid == 0) {
        MBAR_TX(rawbar0, CHUNK_BYTES);
        TMA2D(sb0 + OFF_RAW * 4,               &tmap0, 0,  m * LW, rawbar0);
        TMA2D(sb0 + (OFF_RAW + 1024) * 4,      &tmap1, 0,  m * RW, rawbar0);
        MBAR_TX(rawbar1, CHUNK_BYTES);
        TMA2D(sb0 + (OFF_RAW + RAWSLOT) * 4,        &tmap0, 16, m * LW, rawbar1);
        TMA2D(sb0 + (OFF_RAW + RAWSLOT + 1024) * 4, &tmap1, 16, m * RW, rawbar1);
    }

    // ---- mainloop: 8 chunks x 16 ch; conv f32 -> fp16 (A hi/lo, B hi) ----
    const int gid  = lane >> 2;
    const int ctid = lane & 3;
    const int wm   = warp & 3;
    const int wn   = warp >> 2;
    const int l0   = wm * 16;
    const int nbase = wn * 56;   // wn0: 7 n-tiles, wn1: 6

    float c[7][4];
    #pragma unroll
    for (int j = 0; j < 7; ++j)
        { c[j][0] = 0.f; c[j][1] = 0.f; c[j][2] = 0.f; c[j][3] = 0.f; }

    #pragma unroll 1
    for (int ck = 0; ck < 8; ++ck) {
        const int slot = ck & 1;
        MBAR_WAIT(slot ? rawbar1 : rawbar0, (ck >> 1) & 1);

        {   // convert pass
            const char* rawA = (const char*)(smem + OFF_RAW + slot * RAWSLOT);
            const char* rawB = rawA + 4096;
            u32* AHs = cv + slot * SLOT_W + AH0;
            u32* ALs = cv + slot * SLOT_W + AL0;
            u32* BHs = cv + slot * SLOT_W + BH0;
            const bool lastck = (ck == 7);   // ch 120..127 -> zero
            #pragma unroll
            for (int h2 = 0; h2 < 2; ++h2) {
                int pa = tid + h2 * 256;                 // 512 A pairs
                int row = pa >> 3, p = pa & 7;
                float2 v = *(const float2*)(rawA + SWZ64((u32)(row * 64 + p * 8)));
                u32 hp, lp; f16split2(v.x, v.y, hp, lp);
                if (lastck && p >= 4) { hp = 0u; lp = 0u; }
                AHs[row * CROW + p] = hp;
                ALs[row * CROW + p] = lp;
            }
            #pragma unroll
            for (int h2 = 0; h2 < 4; ++h2) {
                int pb = tid + h2 * 256;                 // 832 B pairs
                if (pb < 832) {
                    int row = pb >> 3, p = pb & 7;
                    float2 v = *(const float2*)(rawB + SWZ64((u32)(row * 64 + p * 8)));
                    u32 hp = f16pack2(v.x, v.y);
                    if (lastck && p >= 4) hp = 0u;
                    BHs[row * CROW + p] = hp;
                }
            }
        }
        __syncthreads();   // conv[slot] published; raw[slot] free

        if (ck < 6 && tid == 0) {
            const u32 rb = slot ? rawbar1 : rawbar0;
            MBAR_TX(rb, CHUNK_BYTES);
            TMA2D(sb0 + (OFF_RAW + slot * RAWSLOT) * 4,        &tmap0, (ck + 2) * 16, m * LW, rb);
            TMA2D(sb0 + (OFF_RAW + slot * RAWSLOT + 1024) * 4, &tmap1, (ck + 2) * 16, m * RW, rb);
        }

        // -- mma: 2-term fp16 (ah*bh + al*bh) --
        {
            const u32* AHp = cv + slot * SLOT_W + AH0;
            const u32* ALp = cv + slot * SLOT_W + AL0;
            const u32* BHp = cv + slot * SLOT_W + BH0;
            const int ar = (l0 + gid) * CROW + ctid;
            u32 ah0 = AHp[ar],     ah1 = AHp[ar + 96];
            u32 ah2 = AHp[ar + 4], ah3 = AHp[ar + 100];
            u32 al0 = ALp[ar],     al1 = ALp[ar + 96];
            u32 al2 = ALp[ar + 4], al3 = ALp[ar + 100];
            const int br = (nbase + gid) * CROW + ctid;
            #pragma unroll
            for (int j = 0; j < 6; ++j) {
                int o = br + j * 96;
                u32 bh0 = BHp[o], bh1 = BHp[o + 4];
                mma_f16(c[j], ah0, ah1, ah2, ah3, bh0, bh1);
                mma_f16(c[j], al0, al1, al2, al3, bh0, bh1);
            }
            if (wn == 0) {                    // uniform 7th tile
                int o = br + 6 * 96;
                u32 bh0 = BHp[o], bh1 = BHp[o + 4];
                mma_f16(c[6], ah0, ah1, ah2, ah3, bh0, bh1);
                mma_f16(c[6], al0, al1, al2, al3, bh0, bh1);
            }
        }
    }
    __syncthreads();   // all conv reads done: conf may alias conv region

    // ---- conf store (x 1/128) + FUSED global Vmax ----
    float vm = -1e30f;
    {
        const float sc = 0.0078125f;
        const int rowa = (l0 + gid) * CSTR + 2 * ctid;
        const int ntiles = wn ? 6 : 7;
        #pragma unroll
        for (int j = 0; j < 7; ++j) {
            if (j < ntiles) {
                int o = rowa + nbase + 8 * j;
                float s0 = c[j][0]*sc, s1 = c[j][1]*sc;
                float s2 = c[j][2]*sc, s3 = c[j][3]*sc;
                *(float2*)&conf[o]            = make_float2(s0, s1);
                *(float2*)&conf[o + 8 * CSTR] = make_float2(s2, s3);
                vm = fmaxf(vm, fmaxf(fmaxf(s0, s1), fmaxf(s2, s3)));
            }
        }
    }
    #pragma unroll
    for (int o = 16; o; o >>= 1) vm = fmaxf(vm, __shfl_xor_sync(~0u, vm, o));
    if (lane == 0) redv[warp] = vm;
    __syncthreads();
    float vmax = redv[0];
    #pragma unroll
    for (int w = 1; w < 8; ++w) vmax = fmaxf(vmax, redv[w]);

    // ---- E pass (in place) + row sums; cols 100..103 excluded ----
    #pragma unroll 2
    for (int q2 = 0; q2 < 8; ++q2) {
        int l = warp * 8 + q2;
        float* row = &conf[l * CSTR];
        float e0 = __expf(row[lane]      - vmax);
        float e1 = __expf(row[lane + 32] - vmax);
        float e2 = __expf(row[lane + 64] - vmax);
        row[lane] = e0; row[lane + 32] = e1; row[lane + 64] = e2;
        float s = e0 + e1 + e2;
        if (lane < 4) {
            float e3 = __expf(row[lane + 96] - vmax);
            row[lane + 96] = e3; s += e3;
        }
        #pragma unroll
        for (int o = 16; o; o >>= 1) s += __shfl_xor_sync(~0u, s, o);
        if (lane == 0) rinv[l] = 1.f / s;
    }
    __syncthreads();

    // ---- col sums: 2 threads per column ----
    {
        int col = tid >> 1, half = tid & 1;
        float s = 0.f;
        const float* p = &conf[(half * 32) * CSTR + col];
        #pragma unroll 8
        for (int l = 0; l < 32; ++l) s += p[l * CSTR];
        float tot = s + __shfl_xor_sync(~0u, s, 1);
        if (!half) cinv[col] = 1.f / tot;
    }
    __syncthreads();

    // ---- cropped sm write + argmax: s = E^2 * rinv * cinv ----
    const int rc = tid & 63;
    const int r  = (rc >> 3) * 10 + (rc & 7) + 11;
    const float ci = cinv[r];
    const int lb = tid >> 6;
    float bv = -1e30f; int bi = 0;
    float* outm = out + (size_t)m * 4096;
    #pragma unroll
    for (int e8 = 0; e8 < 16; ++e8) {
        int l = e8 * 4 + lb;
        float e = conf[l * CSTR + r];
        float s = e * e * rinv[l] * ci;
        int flat = l * 64 + rc;
        outm[flat] = s;
        if (s > bv) { bv = s; bi = flat; }
    }
    #pragma unroll
    for (int o = 16; o; o >>= 1) {
        float v2 = __shfl_xor_sync(~0u, bv, o);
        int   i2 = __shfl_xor_sync(~0u, bi, o);
        if (v2 > bv || (v2 == bv && i2 < bi)) { bv = v2; bi = i2; }
    }
    if (lane == 0) { redv[warp] = bv; redi[warp] = bi; }
    __syncthreads();

    // ---- warp 0: final reduce + epilogue ----
    if (warp == 0) {
        float v = (lane < 8) ? redv[lane] : -1e30f;
        int   i = (lane < 8) ? redi[lane] : 0x7fffffff;
        #pragma unroll
        for (int o = 4; o; o >>= 1) {
            float v2 = __shfl_xor_sync(~0u, v, o);
            int   i2 = __shfl_xor_sync(~0u, i, o);
            if (v2 > v || (v2 == v && i2 < i)) { v = v2; i = i2; }
        }
        if (lane == 0) {
            int idx = i;
            int il = idx >> 6, ir = idx & 63;
            float dlx = (float)(il & 7) - 3.5f, dly = (float)(il >> 3) - 3.5f;
            float drx = (float)(ir & 7) - 3.5f, dry = (float)(ir >> 3) - 3.5f;

            float4 av0 = __ldg((const float4*)(f0base + il * CD + 120));
            float4 av1 = __ldg((const float4*)(f0base + il * CD + 124));
            float av[8] = {av0.x, av0.y, av0.z, av0.w, av1.x, av1.y, av1.z, av1.w};

            // ff from raw slot1 B box (chunk 7 = ch 112..127): ch 120+t -> col 8+t
            const char* ffbox = (const char*)(smem + OFF_RAW + RAWSLOT + 1024);
            float p[9];
            int ib = ir >> 3, jb = ir & 7;
            #pragma unroll
            for (int di = 0; di < 3; ++di) {
                int ii = ib + di - 1; ii = (ii < 0) ? ii + 10 : ((ii > 9) ? ii - 10 : ii);
                #pragma unroll
                for (int dj = 0; dj < 3; ++dj) {
                    int jj = jb + dj - 1; jj = (jj < 0) ? jj + 10 : ((jj > 9) ? jj - 10 : jj);
                    int rr2 = ii * 10 + jj;
                    float s = 0.f;
                    #pragma unroll
                    for (int t = 0; t < 8; ++t)
                        s += av[t] * *(const float*)(ffbox + SWZ64((u32)(rr2 * 64 + (8 + t) * 4)));
                    p[di * 3 + dj] = s;
                }
            }
            float mx = p[0];
            #pragma unroll
            for (int t = 1; t < 9; ++t) mx = fmaxf(mx, p[t]);
            const float escale = 0.035355339059327373f;  // (1/sqrt8)/TEMP
            float h[9], se = 0.f;
            #pragma unroll
            for (int t = 0; t < 9; ++t) { h[t] = __expf((p[t] - mx) * escale); se += h[t]; }
            float inv = 1.f / se;
            float ex = 0.f, ey = 0.f;
            #pragma unroll
            for (int di = 0; di < 3; ++di)
                #pragma unroll
                for (int dj = 0; dj < 3; ++dj) {
                    ex += h[di * 3 + dj] * (float)(dj - 1);
                    ey += h[di * 3 + dj] * (float)(di - 1);
                }
            ex *= inv; ey *= inv;

            float mk0x = mk0[2 * m], mk0y = mk0[2 * m + 1];
            float mk1x = mk1[2 * m], mk1y = mk1[2 * m + 1];
            size_t base = (size_t)MTOT * 4096;
            out[base + 2 * m]     = mk0x + dlx * 2.f;
            out[base + 2 * m + 1] = mk0y + dly * 2.f;
            out[base + 2 * MTOT + 2 * m]     = mk1x + drx * 2.f + ex * 2.f;
            out[base + 2 * MTOT + 2 * m + 1] = mk1y + dry * 2.f + ey * 2.f;
        }
    }
}

typedef CUresult (*PFN_encodeTiled)(
    CUtensorMap*, CUtensorMapDataType, cuuint32_t, void*,
    const cuuint64_t*, const cuuint64_t*, const cuuint32_t*, const cuuint32_t*,
    CUtensorMapInterleave, CUtensorMapSwizzle, CUtensorMapL2promotion,
    CUtensorMapFloatOOBfill);

extern "C" void kernel_launch(void* const* d_in, const int* in_sizes, int n_in,
                              void* d_out, int out_size)
{
    const float* feat0 = (const float*)d_in[0];
    const float* feat1 = (const float*)d_in[1];
    const float* mk0   = (const float*)d_in[2];
    const float* mk1   = (const float*)d_in[3];
    float* out = (float*)d_out;

    void* fn = nullptr;
    cudaDriverEntryPointQueryResult qres;
    cudaGetDriverEntryPoint("cuTensorMapEncodeTiled", &fn, cudaEnableDefault, &qres);
    PFN_encodeTiled enc = (PFN_encodeTiled)fn;

    CUtensorMap map0, map1;
    {
        cuuint64_t dims[2] = {CD, (cuuint64_t)MTOT * LW};
        cuuint64_t strd[1] = {CD * 4};
        cuuint32_t box[2]  = {16, LW};
        cuuint32_t els[2]  = {1, 1};
        enc(&map0, CU_TENSOR_MAP_DATA_TYPE_FLOAT32, 2, (void*)feat0,
            dims, strd, box, els, CU_TENSOR_MAP_INTERLEAVE_NONE,
            CU_TENSOR_MAP_SWIZZLE_64B, CU_TENSOR_MAP_L2_PROMOTION_L2_128B,
            CU_TENSOR_MAP_FLOAT_OOB_FILL_NONE);
    }
    {
        cuuint64_t dims[2] = {CD, (cuuint64_t)MTOT * RW};
        cuuint64_t strd[1] = {CD * 4};
        cuuint32_t box[2]  = {16, 104};
        cuuint32_t els[2]  = {1, 1};
        enc(&map1, CU_TENSOR_MAP_DATA_TYPE_FLOAT32, 2, (void*)feat1,
            dims, strd, box, els, CU_TENSOR_MAP_INTERLEAVE_NONE,
            CU_TENSOR_MAP_SWIZZLE_64B, CU_TENSOR_MAP_L2_PROMOTION_L2_128B,
            CU_TENSOR_MAP_FLOAT_OOB_FILL_NONE);
    }

    cudaFuncSetAttribute(fine_matching_kernel,
                         cudaFuncAttributeMaxDynamicSharedMemorySize, SMEM_BYTES);
    fine_matching_kernel<<<MTOT, 256, SMEM_BYTES>>>(feat0, feat1, mk0, mk1, out,
                                                    map0, map1);
}